// round 4
// baseline (speedup 1.0000x reference)
#include <cuda_runtime.h>

#define BB 64
#define NN 576
#define DD 768
#define KK 1024
#define NT 2
#define ROWS (BB * NN)          // 36864
#define NPAIR (BB * KK)         // 65536
#define OUT_MAIN (NPAIR * NT)   // 131072
#define NV4 (DD / 4)            // 192 float4 per row

// Per-row projections P[b*N+n] = {z.W0[:,0], z.W0[:,1], z.W1[:,0], z.W1[:,1]}
// where W0 = W[0:D,:], W1 = W[D:2D,:]. 576 KB static scratch (guard-safe).
__device__ float4 g_P[ROWS];

// Kernel 1: skinny projection GEMM [36864x768]x[768x4].
// Warp processes 4 consecutive rows per iteration; weights in smem with
// component-major layout Wc[c][i4] -> conflict-free LDS.128 (16B lane stride),
// each weight fetch amortized over 4 rows. ~65 regs -> 3 blocks/SM, one wave.
__global__ __launch_bounds__(256) void partvit_project_kernel(
    const float* __restrict__ z, const float* __restrict__ W) {
    // Wc[c][i4] = {W[d][0], W[d][1], W[d+D][0], W[d+D][1]}, d = 4*i4 + c. 12 KB.
    __shared__ float4 Wc[4][NV4];
    for (int f = threadIdx.x; f < DD; f += 256) {
        int c = f / NV4, i4 = f - c * NV4;
        int d = 4 * i4 + c;
        Wc[c][i4] = make_float4(W[2 * d], W[2 * d + 1],
                                W[2 * (d + DD)], W[2 * (d + DD) + 1]);
    }
    __syncthreads();

    int lane = threadIdx.x & 31;
    int gw   = (blockIdx.x * blockDim.x + threadIdx.x) >> 5;
    int nw   = (gridDim.x * blockDim.x) >> 5;   // 3072 warps -> 3 iters each

    for (int it = gw; it < ROWS / 4; it += nw) {
        int row = it * 4;
        const float4* z4 = reinterpret_cast<const float4*>(z + (size_t)row * DD);

        float4 acc[4] = {{0,0,0,0},{0,0,0,0},{0,0,0,0},{0,0,0,0}};
        #pragma unroll
        for (int j = 0; j < 6; j++) {
            int i4 = lane + 32 * j;
            float4 w0 = Wc[0][i4];
            float4 w1 = Wc[1][i4];
            float4 w2 = Wc[2][i4];
            float4 w3 = Wc[3][i4];
            #pragma unroll
            for (int r = 0; r < 4; r++) {
                float4 zv = z4[r * NV4 + i4];
                acc[r].x += zv.x * w0.x + zv.y * w1.x + zv.z * w2.x + zv.w * w3.x;
                acc[r].y += zv.x * w0.y + zv.y * w1.y + zv.z * w2.y + zv.w * w3.y;
                acc[r].z += zv.x * w0.z + zv.y * w1.z + zv.z * w2.z + zv.w * w3.z;
                acc[r].w += zv.x * w0.w + zv.y * w1.w + zv.z * w2.w + zv.w * w3.w;
            }
        }

        #pragma unroll
        for (int r = 0; r < 4; r++) {
            #pragma unroll
            for (int off = 16; off; off >>= 1) {
                acc[r].x += __shfl_xor_sync(0xffffffffu, acc[r].x, off);
                acc[r].y += __shfl_xor_sync(0xffffffffu, acc[r].y, off);
                acc[r].z += __shfl_xor_sync(0xffffffffu, acc[r].z, off);
                acc[r].w += __shfl_xor_sync(0xffffffffu, acc[r].w, off);
            }
        }
        if (lane == 0) {
            g_P[row + 0] = acc[0];
            g_P[row + 1] = acc[1];
            g_P[row + 2] = acc[2];
            g_P[row + 3] = acc[3];
        }
    }
}

// Kernel 2: gather pairs of projections + bias. One thread per (b,k) pair,
// 65536 threads for occupancy (latency-bound stage). Indices are int32.
__global__ __launch_bounds__(256) void partvit_gather_kernel(
    const int* __restrict__ idx, const float* __restrict__ bh,
    float* __restrict__ out, int out_size) {
    int i = blockIdx.x * 256 + threadIdx.x;    // pair id in [0, B*K)
    if (i >= NPAIR) return;
    int b = i >> 10;                            // i / KK

    int2 p = reinterpret_cast<const int2*>(idx)[i];
    int i0 = min(max(p.x, 0), NN - 1);
    int i1 = min(max(p.y, 0), NN - 1);

    float4 p0 = g_P[b * NN + i0];   // pair elem 0 -> W[0:D] halves (.x,.y)
    float4 p1 = g_P[b * NN + i1];   // pair elem 1 -> W[D:2D] halves (.z,.w)

    float2 o;
    o.x = p0.x + p1.z + bh[0];
    o.y = p0.y + p1.w + bh[1];
    reinterpret_cast<float2*>(out)[i] = o;

    // If the harness flattens the (out, indices) tuple, echo indices as f32.
    if (out_size >= OUT_MAIN + 2 * NPAIR) {
        out[OUT_MAIN + 2 * i + 0] = (float)p.x;
        out[OUT_MAIN + 2 * i + 1] = (float)p.y;
    }
}

extern "C" void kernel_launch(void* const* d_in, const int* in_sizes, int n_in,
                              void* d_out, int out_size) {
    const float* z   = (const float*)d_in[0];      // [B, N, D] f32
    const int*   idx = (const int*)d_in[1];        // [B, K, 2] i32
    const float* W   = (const float*)d_in[2];      // [2D, NT] f32
    const float* bh  = (const float*)d_in[3];      // [NT] f32
    float* out = (float*)d_out;

    partvit_project_kernel<<<384, 256>>>(z, W);    // 3072 warps, 3 iters each
    partvit_gather_kernel<<<NPAIR / 256, 256>>>(idx, bh, out, out_size);
}

// round 5
// speedup vs baseline: 3.8312x; 3.8312x over previous
#include <cuda_runtime.h>

#define BB 64
#define NN 576
#define DD 768
#define KK 1024
#define NT 2
#define ROWS (BB * NN)          // 36864
#define NPAIR (BB * KK)         // 65536
#define OUT_MAIN (NPAIR * NT)   // 131072
#define NV4 (DD / 4)            // 192 float4 per row

// Per-row projections P[b*N+n] = {z.W0[:,0], z.W0[:,1], z.W1[:,0], z.W1[:,1]}
// where W0 = W[0:D,:], W1 = W[D:2D,:]. 576 KB static scratch (guard-safe).
__device__ float4 g_P[ROWS];

// Kernel 1: skinny projection GEMM [36864x768]x[768x4].
// Warp = 4 consecutive rows per iter. Weights in smem, component-major
// Wc[c][i4] -> LDS.128 with 16B lane stride (conflict-free), amortized x4 rows.
// j-loop NOT unrolled + launch_bounds(256,4): regs <= 64, no spills, 32 warps/SM.
__global__ __launch_bounds__(256, 4) void partvit_project_kernel(
    const float* __restrict__ z, const float* __restrict__ W) {
    // Wc[c][i4] = {W[d][0], W[d][1], W[d+D][0], W[d+D][1]}, d = 4*i4 + c. 12 KB.
    __shared__ float4 Wc[4][NV4];
    for (int f = threadIdx.x; f < DD; f += 256) {
        int c = f / NV4, i4 = f - c * NV4;
        int d = 4 * i4 + c;
        Wc[c][i4] = make_float4(W[2 * d], W[2 * d + 1],
                                W[2 * (d + DD)], W[2 * (d + DD) + 1]);
    }
    __syncthreads();

    int lane = threadIdx.x & 31;
    int gw   = (blockIdx.x * blockDim.x + threadIdx.x) >> 5;
    int nw   = (gridDim.x * blockDim.x) >> 5;   // 3072 warps -> exactly 3 iters

    for (int it = gw; it < ROWS / 4; it += nw) {
        int row = it * 4;
        const float4* z4 = reinterpret_cast<const float4*>(z + (size_t)row * DD);

        float4 a0 = {0,0,0,0}, a1 = {0,0,0,0}, a2 = {0,0,0,0}, a3 = {0,0,0,0};
        #pragma unroll 1
        for (int j = 0; j < 6; j++) {
            int i4 = lane + 32 * j;
            float4 z0 = z4[0 * NV4 + i4];
            float4 z1 = z4[1 * NV4 + i4];
            float4 z2 = z4[2 * NV4 + i4];
            float4 z3 = z4[3 * NV4 + i4];
            float4 w0 = Wc[0][i4];
            float4 w1 = Wc[1][i4];
            float4 w2 = Wc[2][i4];
            float4 w3 = Wc[3][i4];
            a0.x += z0.x*w0.x + z0.y*w1.x + z0.z*w2.x + z0.w*w3.x;
            a0.y += z0.x*w0.y + z0.y*w1.y + z0.z*w2.y + z0.w*w3.y;
            a0.z += z0.x*w0.z + z0.y*w1.z + z0.z*w2.z + z0.w*w3.z;
            a0.w += z0.x*w0.w + z0.y*w1.w + z0.z*w2.w + z0.w*w3.w;
            a1.x += z1.x*w0.x + z1.y*w1.x + z1.z*w2.x + z1.w*w3.x;
            a1.y += z1.x*w0.y + z1.y*w1.y + z1.z*w2.y + z1.w*w3.y;
            a1.z += z1.x*w0.z + z1.y*w1.z + z1.z*w2.z + z1.w*w3.z;
            a1.w += z1.x*w0.w + z1.y*w1.w + z1.z*w2.w + z1.w*w3.w;
            a2.x += z2.x*w0.x + z2.y*w1.x + z2.z*w2.x + z2.w*w3.x;
            a2.y += z2.x*w0.y + z2.y*w1.y + z2.z*w2.y + z2.w*w3.y;
            a2.z += z2.x*w0.z + z2.y*w1.z + z2.z*w2.z + z2.w*w3.z;
            a2.w += z2.x*w0.w + z2.y*w1.w + z2.z*w2.w + z2.w*w3.w;
            a3.x += z3.x*w0.x + z3.y*w1.x + z3.z*w2.x + z3.w*w3.x;
            a3.y += z3.x*w0.y + z3.y*w1.y + z3.z*w2.y + z3.w*w3.y;
            a3.z += z3.x*w0.z + z3.y*w1.z + z3.z*w2.z + z3.w*w3.z;
            a3.w += z3.x*w0.w + z3.y*w1.w + z3.z*w2.w + z3.w*w3.w;
        }

        #pragma unroll
        for (int off = 16; off; off >>= 1) {
            a0.x += __shfl_xor_sync(0xffffffffu, a0.x, off);
            a0.y += __shfl_xor_sync(0xffffffffu, a0.y, off);
            a0.z += __shfl_xor_sync(0xffffffffu, a0.z, off);
            a0.w += __shfl_xor_sync(0xffffffffu, a0.w, off);
            a1.x += __shfl_xor_sync(0xffffffffu, a1.x, off);
            a1.y += __shfl_xor_sync(0xffffffffu, a1.y, off);
            a1.z += __shfl_xor_sync(0xffffffffu, a1.z, off);
            a1.w += __shfl_xor_sync(0xffffffffu, a1.w, off);
            a2.x += __shfl_xor_sync(0xffffffffu, a2.x, off);
            a2.y += __shfl_xor_sync(0xffffffffu, a2.y, off);
            a2.z += __shfl_xor_sync(0xffffffffu, a2.z, off);
            a2.w += __shfl_xor_sync(0xffffffffu, a2.w, off);
            a3.x += __shfl_xor_sync(0xffffffffu, a3.x, off);
            a3.y += __shfl_xor_sync(0xffffffffu, a3.y, off);
            a3.z += __shfl_xor_sync(0xffffffffu, a3.z, off);
            a3.w += __shfl_xor_sync(0xffffffffu, a3.w, off);
        }
        if (lane == 0) {
            g_P[row + 0] = a0;
            g_P[row + 1] = a1;
            g_P[row + 2] = a2;
            g_P[row + 3] = a3;
        }
    }
}

// Kernel 2: gather pairs of projections + bias. One thread per (b,k) pair.
// P (576 KB) is L2-resident after kernel 1. Indices are int32.
__global__ __launch_bounds__(256) void partvit_gather_kernel(
    const int* __restrict__ idx, const float* __restrict__ bh,
    float* __restrict__ out, int out_size) {
    int i = blockIdx.x * 256 + threadIdx.x;    // pair id in [0, B*K)
    if (i >= NPAIR) return;
    int b = i >> 10;                            // i / KK

    int2 p = reinterpret_cast<const int2*>(idx)[i];
    int i0 = min(max(p.x, 0), NN - 1);
    int i1 = min(max(p.y, 0), NN - 1);

    float4 p0 = g_P[b * NN + i0];   // pair elem 0 -> W[0:D] halves (.x,.y)
    float4 p1 = g_P[b * NN + i1];   // pair elem 1 -> W[D:2D] halves (.z,.w)

    float2 o;
    o.x = p0.x + p1.z + bh[0];
    o.y = p0.y + p1.w + bh[1];
    reinterpret_cast<float2*>(out)[i] = o;

    // If the harness flattens the (out, indices) tuple, echo indices as f32.
    if (out_size >= OUT_MAIN + 2 * NPAIR) {
        out[OUT_MAIN + 2 * i + 0] = (float)p.x;
        out[OUT_MAIN + 2 * i + 1] = (float)p.y;
    }
}

extern "C" void kernel_launch(void* const* d_in, const int* in_sizes, int n_in,
                              void* d_out, int out_size) {
    const float* z   = (const float*)d_in[0];      // [B, N, D] f32
    const int*   idx = (const int*)d_in[1];        // [B, K, 2] i32
    const float* W   = (const float*)d_in[2];      // [2D, NT] f32
    const float* bh  = (const float*)d_in[3];      // [NT] f32
    float* out = (float*)d_out;

    partvit_project_kernel<<<384, 256>>>(z, W);    // 3072 warps, 3 iters each
    partvit_gather_kernel<<<NPAIR / 256, 256>>>(idx, bh, out, out_size);
}